// round 15
// baseline (speedup 1.0000x reference)
#include <cuda_runtime.h>
#include <cuda_bf16.h>
#include <cuda_fp16.h>
#include <math.h>
#include <stdint.h>

#define BB 32
#define TT 1024
#define JJ 256
#define DD 512
#define NCHUNK 8

// ---------------- scratch (device globals) ----------------------------------
__device__ float g_S[BB * TT * JJ];      // raw S (32 MB)
__device__ __half g_Qh[BB * JJ * DD];    // Q pre-converted to fp16 (8 MB)
__device__ __half g_Ph[BB * TT * JJ];    // P = softmax(S) fp16 (16 MB)
__device__ float g_q2[BB * JJ];
__device__ float g_mp[BB * 2 * TT];      // row-max partials (per j-tile)
__device__ float g_pM[BB * NCHUNK * JJ];
__device__ float g_pZ[BB * NCHUNK * JJ];
__device__ float g_M[BB * JJ];
__device__ float g_invZ[BB * JJ];
__device__ float g_bt[BB * TT];
__device__ float g_hp[BB * NCHUNK * DD];
__device__ float g_h[BB * DD];

// ---------------- helpers ----------------------------------------------------
__device__ __forceinline__ uint32_t smem_u32(const void* p) {
    uint32_t a;
    asm("{ .reg .u64 t; cvta.to.shared.u64 t, %1; cvt.u32.u64 %0, t; }" : "=r"(a) : "l"(p));
    return a;
}
__device__ __forceinline__ void cpa16(uint32_t dst, const void* src) {
    asm volatile("cp.async.cg.shared.global [%0], [%1], 16;" :: "r"(dst), "l"(src));
}
__device__ __forceinline__ void cpa_commit() {
    asm volatile("cp.async.commit_group;" ::: "memory");
}
template <int N>
__device__ __forceinline__ void cpa_wait() {
    asm volatile("cp.async.wait_group %0;" :: "n"(N) : "memory");
}
__device__ __forceinline__ void ldmx4(uint32_t* r, uint32_t a) {
    asm volatile("ldmatrix.sync.aligned.m8n8.x4.shared.b16 {%0,%1,%2,%3}, [%4];"
                 : "=r"(r[0]), "=r"(r[1]), "=r"(r[2]), "=r"(r[3]) : "r"(a));
}
__device__ __forceinline__ void ldmx4t(uint32_t* r, uint32_t a) {
    asm volatile("ldmatrix.sync.aligned.m8n8.x4.trans.shared.b16 {%0,%1,%2,%3}, [%4];"
                 : "=r"(r[0]), "=r"(r[1]), "=r"(r[2]), "=r"(r[3]) : "r"(a));
}
__device__ __forceinline__ void mma_f16(float* c, const uint32_t* a, uint32_t b0, uint32_t b1) {
    asm volatile(
        "mma.sync.aligned.m16n8k16.row.col.f32.f16.f16.f32 "
        "{%0,%1,%2,%3}, {%4,%5,%6,%7}, {%8,%9}, {%0,%1,%2,%3};"
        : "+f"(c[0]), "+f"(c[1]), "+f"(c[2]), "+f"(c[3])
        : "r"(a[0]), "r"(a[1]), "r"(a[2]), "r"(a[3]), "r"(b0), "r"(b1));
}
// fp16 convert 8 floats -> 16B
__device__ __forceinline__ void cvtf16_8(const float* v, uint4* hi) {
    uint32_t h[4];
#pragma unroll
    for (int p = 0; p < 4; p++)
        asm("cvt.rn.f16x2.f32 %0, %1, %2;" : "=r"(h[p]) : "f"(v[2 * p + 1]), "f"(v[2 * p]));
    *hi = make_uint4(h[0], h[1], h[2], h[3]);
}

// ---------------- prepQ: Qh = fp16(Q), q2 = Q @ w2 (one pass) ----------------
__global__ __launch_bounds__(256) void k_prepQ(const float* __restrict__ Q,
                                               const float* __restrict__ w2,
                                               float* __restrict__ q2out) {
    const int wid = threadIdx.x >> 5, lane = threadIdx.x & 31;
    const int row = blockIdx.x * 8 + wid;
    const float* src = Q + (size_t)row * DD;
    __half* dst = g_Qh + (size_t)row * DD;
    float s = 0.f;
#pragma unroll
    for (int h = 0; h < 2; h++) {
        const int c = h * 256 + lane * 8;
        float4 v0 = *(const float4*)(src + c);
        float4 v1 = *(const float4*)(src + c + 4);
        float v[8] = {v0.x, v0.y, v0.z, v0.w, v1.x, v1.y, v1.z, v1.w};
#pragma unroll
        for (int e = 0; e < 8; e++) s = fmaf(v[e], __ldg(&w2[c + e]), s);
        uint4 hi;
        cvtf16_8(v, &hi);
        *(uint4*)(dst + c) = hi;
    }
#pragma unroll
    for (int o = 16; o > 0; o >>= 1) s += __shfl_down_sync(0xffffffffu, s, o);
    if (lane == 0) q2out[row] = s;
}

// ---------------- S-GEMM: S = (C.*w3)@Q^T + c1 + q2, fused c1 + stats --------
#define SG_STAGE 16384
#define SG_B_OFF 8192
__global__ __launch_bounds__(256, 2) void k_s_mma(const float* __restrict__ C,
                                                  const float* __restrict__ wa) {
    extern __shared__ __align__(16) char dsm[];
    __shared__ float w1s[512];
    __shared__ float w3s[512];
    __shared__ float c1s[128], q2s[128];
    __shared__ float sRM[4][128];
    __shared__ float sCM[2][128], sCZ[2][128];

    const int tid = threadIdx.x, lane = tid & 31, wid = tid >> 5;
    const int b = blockIdx.z, tb = blockIdx.y, jt = blockIdx.x;
    const int t0 = tb * 128, j0 = jt * 128;

    w1s[tid] = wa[tid];
    w1s[tid + 256] = wa[tid + 256];
    w3s[tid] = wa[1024 + tid];
    w3s[tid + 256] = wa[1024 + tid + 256];
    if (tid < 128) q2s[tid] = g_q2[b * JJ + j0 + tid];
    __syncthreads();

    const uint32_t smb = smem_u32(dsm);
    const int sr = tid >> 2, sc = tid & 3;
    const int ssw = (sr >> 1) & 3;
    const float* Ab = C + ((size_t)(b * TT + t0 + sr)) * DD + sc * 8;
    const __half* Bb = g_Qh + ((size_t)(b * JJ + j0 + sr)) * DD + sc * 8;
    const uint32_t stsA = sr * 64 + ((sc ^ ssw) << 4);
    const uint32_t stsB = SG_B_OFF + sr * 64 + ((sc ^ ssw) << 4);

    float cd0 = 0.f, cd1 = 0.f;   // c1 partial dots for rows sr, sr+64

    float ra[16];
    // load A chunk 0
    {
        *(float4*)(ra) = *(const float4*)(Ab);
        *(float4*)(ra + 4) = *(const float4*)(Ab + 4);
        *(float4*)(ra + 8) = *(const float4*)(Ab + (size_t)64 * DD);
        *(float4*)(ra + 12) = *(const float4*)(Ab + (size_t)64 * DD + 4);
    }
    // stage chunk 0: A convert+STS (+c1 fma), B via cp.async
    {
        const float* w = &w3s[sc * 8];
        const float* w1 = &w1s[sc * 8];
        float va[8];
        uint4 hi;
#pragma unroll
        for (int e = 0; e < 8; e++) { cd0 = fmaf(ra[e], w1[e], cd0); va[e] = ra[e] * w[e]; }
        cvtf16_8(va, &hi);
        *(uint4*)(dsm + stsA) = hi;
#pragma unroll
        for (int e = 0; e < 8; e++) { cd1 = fmaf(ra[8 + e], w1[e], cd1); va[e] = ra[8 + e] * w[e]; }
        cvtf16_8(va, &hi);
        *(uint4*)(dsm + stsA + 64 * 64) = hi;
        cpa16(smb + stsB, Bb);
        cpa16(smb + stsB + 64 * 64, Bb + (size_t)64 * DD);
        cpa_commit();
    }
    // load A chunk 1
    {
        const float* pa = Ab + 32;
        *(float4*)(ra) = *(const float4*)(pa);
        *(float4*)(ra + 4) = *(const float4*)(pa + 4);
        *(float4*)(ra + 8) = *(const float4*)(pa + (size_t)64 * DD);
        *(float4*)(ra + 12) = *(const float4*)(pa + (size_t)64 * DD + 4);
    }
    cpa_wait<0>();
    __syncthreads();

    const int wm = wid >> 2, wn = wid & 3;
    float acc[4][4][4];
#pragma unroll
    for (int i = 0; i < 4; i++)
#pragma unroll
        for (int j = 0; j < 4; j++)
#pragma unroll
            for (int e = 0; e < 4; e++) acc[i][j][e] = 0.f;

    const int arow = wm * 64 + (lane & 7) + ((lane >> 3) & 1) * 8;
    const int aswz = (arow >> 1) & 3;
    const int ack = lane >> 4;
    const int bj = wn * 32 + (lane & 7) + ((lane >> 4) & 1) * 8;
    const int bsw3 = (bj >> 1) & 3;
    const int bck = (lane >> 3) & 1;

#pragma unroll 1
    for (int kc = 0; kc < 16; kc++) {
        if (kc < 15) {
            char* st = dsm + ((kc + 1) & 1) * SG_STAGE;
            const uint32_t stb = smb + ((kc + 1) & 1) * SG_STAGE;
            const float* w = &w3s[(kc + 1) * 32 + sc * 8];
            const float* w1 = &w1s[(kc + 1) * 32 + sc * 8];
            float va[8];
            uint4 hi;
#pragma unroll
            for (int e = 0; e < 8; e++) { cd0 = fmaf(ra[e], w1[e], cd0); va[e] = ra[e] * w[e]; }
            cvtf16_8(va, &hi);
            *(uint4*)(st + stsA) = hi;
#pragma unroll
            for (int e = 0; e < 8; e++) { cd1 = fmaf(ra[8 + e], w1[e], cd1); va[e] = ra[8 + e] * w[e]; }
            cvtf16_8(va, &hi);
            *(uint4*)(st + stsA + 64 * 64) = hi;
            cpa16(stb + stsB, Bb + (kc + 1) * 32);
            cpa16(stb + stsB + 64 * 64, Bb + (kc + 1) * 32 + (size_t)64 * DD);
            cpa_commit();
        }
        if (kc < 14) {
            const float* pa = Ab + (kc + 2) * 32;
            *(float4*)(ra) = *(const float4*)(pa);
            *(float4*)(ra + 4) = *(const float4*)(pa + 4);
            *(float4*)(ra + 8) = *(const float4*)(pa + (size_t)64 * DD);
            *(float4*)(ra + 12) = *(const float4*)(pa + (size_t)64 * DD + 4);
        }
        const uint32_t sb = smb + (kc & 1) * SG_STAGE;
#pragma unroll
        for (int ks = 0; ks < 2; ks++) {
            uint32_t Af[4][4], Bf[2][4];
            const int ca = ks * 2 + ack;
            const int cb = ks * 2 + bck;
#pragma unroll
            for (int mi = 0; mi < 4; mi++)
                ldmx4(Af[mi], sb + (uint32_t)(arow + mi * 16) * 64 + ((ca ^ aswz) << 4));
#pragma unroll
            for (int n2 = 0; n2 < 2; n2++)
                ldmx4(Bf[n2], sb + SG_B_OFF + (uint32_t)(bj + n2 * 16) * 64 + ((cb ^ bsw3) << 4));
#pragma unroll
            for (int mi = 0; mi < 4; mi++)
#pragma unroll
                for (int ni = 0; ni < 4; ni++) {
                    const uint32_t* bp = &Bf[ni >> 1][(ni & 1) * 2];
                    mma_f16(acc[mi][ni], Af[mi], bp[0], bp[1]);
                }
        }
        cpa_wait<0>();
        __syncthreads();
    }

    // reduce c1 partials across the 4 sc-threads of each row
    cd0 += __shfl_xor_sync(0xffffffffu, cd0, 1);
    cd0 += __shfl_xor_sync(0xffffffffu, cd0, 2);
    cd1 += __shfl_xor_sync(0xffffffffu, cd1, 1);
    cd1 += __shfl_xor_sync(0xffffffffu, cd1, 2);
    if ((tid & 3) == 0) {
        c1s[sr] = cd0;
        c1s[sr + 64] = cd1;
    }
    __syncthreads();

    // ---- epilogue: biases, store S, fused row-max + column partial stats ----
    const int g = lane >> 2, tc = (lane & 3) * 2;
#pragma unroll
    for (int mi = 0; mi < 4; mi++) {
        const int tl = wm * 64 + mi * 16 + g;
        const float c1a = c1s[tl], c1b = c1s[tl + 8];
        float* row0 = &g_S[((size_t)(b * TT + t0 + tl)) * JJ + j0];
        float* row1 = row0 + (size_t)8 * JJ;
#pragma unroll
        for (int ni = 0; ni < 4; ni++) {
            const int jl = wn * 32 + ni * 8 + tc;
            const float q2a = q2s[jl], q2b = q2s[jl + 1];
            acc[mi][ni][0] += c1a + q2a;
            acc[mi][ni][1] += c1a + q2b;
            acc[mi][ni][2] += c1b + q2a;
            acc[mi][ni][3] += c1b + q2b;
            *(float2*)(row0 + jl) = make_float2(acc[mi][ni][0], acc[mi][ni][1]);
            *(float2*)(row1 + jl) = make_float2(acc[mi][ni][2], acc[mi][ni][3]);
        }
    }
#pragma unroll
    for (int mi = 0; mi < 4; mi++) {
#pragma unroll
        for (int rr = 0; rr < 2; rr++) {
            float m = -1e30f;
#pragma unroll
            for (int ni = 0; ni < 4; ni++)
                m = fmaxf(m, fmaxf(acc[mi][ni][rr * 2], acc[mi][ni][rr * 2 + 1]));
            m = fmaxf(m, __shfl_xor_sync(0xffffffffu, m, 1));
            m = fmaxf(m, __shfl_xor_sync(0xffffffffu, m, 2));
            if ((lane & 3) == 0) sRM[wn][wm * 64 + mi * 16 + g + rr * 8] = m;
        }
    }
#pragma unroll
    for (int ni = 0; ni < 4; ni++) {
#pragma unroll
        for (int cc = 0; cc < 2; cc++) {
            float m = -1e30f;
#pragma unroll
            for (int mi = 0; mi < 4; mi++)
                m = fmaxf(m, fmaxf(acc[mi][ni][cc], acc[mi][ni][2 + cc]));
            float z = 0.f;
#pragma unroll
            for (int mi = 0; mi < 4; mi++)
                z += __expf(acc[mi][ni][cc] - m) + __expf(acc[mi][ni][2 + cc] - m);
#pragma unroll
            for (int o = 4; o < 32; o <<= 1) {
                float Mo = __shfl_xor_sync(0xffffffffu, m, o);
                float Zo = __shfl_xor_sync(0xffffffffu, z, o);
                float nm = fmaxf(m, Mo);
                z = z * __expf(m - nm) + Zo * __expf(Mo - nm);
                m = nm;
            }
            if (g == 0) {
                sCM[wm][wn * 32 + ni * 8 + tc + cc] = m;
                sCZ[wm][wn * 32 + ni * 8 + tc + cc] = z;
            }
        }
    }
    __syncthreads();
    if (tid < 128) {
        float m = fmaxf(fmaxf(sRM[0][tid], sRM[1][tid]), fmaxf(sRM[2][tid], sRM[3][tid]));
        g_mp[((size_t)(b * 2 + jt)) * TT + t0 + tid] = m;
        float M0 = sCM[0][tid], M1 = sCM[1][tid];
        float nm = fmaxf(M0, M1);
        float Z = sCZ[0][tid] * __expf(M0 - nm) + sCZ[1][tid] * __expf(M1 - nm);
        g_pM[(b * NCHUNK + tb) * JJ + j0 + tid] = nm;
        g_pZ[(b * NCHUNK + tb) * JJ + j0 + tid] = Z;
    }
}

// ---------------- merged stats: colcombine + bt -------------------------------
__global__ __launch_bounds__(256) void k_stats() {
    __shared__ float red[256];
    int b = blockIdx.x, tid = threadIdx.x;
    {
        int j = tid;
        float M = -1e30f;
#pragma unroll
        for (int c = 0; c < NCHUNK; c++) M = fmaxf(M, g_pM[(b * NCHUNK + c) * JJ + j]);
        float Z = 0.f;
#pragma unroll
        for (int c = 0; c < NCHUNK; c++)
            Z += g_pZ[(b * NCHUNK + c) * JJ + j] * __expf(g_pM[(b * NCHUNK + c) * JJ + j] - M);
        g_M[b * JJ + j] = M;
        g_invZ[b * JJ + j] = 1.0f / Z;
    }
    float mv[4];
#pragma unroll
    for (int i = 0; i < 4; i++) {
        int t = tid + i * 256;
        mv[i] = fmaxf(g_mp[((size_t)(b * 2)) * TT + t], g_mp[((size_t)(b * 2 + 1)) * TT + t]);
    }
    float mx = fmaxf(fmaxf(mv[0], mv[1]), fmaxf(mv[2], mv[3]));
    red[tid] = mx;
    __syncthreads();
    for (int s = 128; s > 0; s >>= 1) {
        if (tid < s) red[tid] = fmaxf(red[tid], red[tid + s]);
        __syncthreads();
    }
    float bmax = red[0];
    __syncthreads();
    float e[4], ssum = 0.f;
#pragma unroll
    for (int i = 0; i < 4; i++) { e[i] = __expf(mv[i] - bmax); ssum += e[i]; }
    red[tid] = ssum;
    __syncthreads();
    for (int s = 128; s > 0; s >>= 1) {
        if (tid < s) red[tid] += red[tid + s];
        __syncthreads();
    }
    float inv = 1.0f / red[0];
#pragma unroll
    for (int i = 0; i < 4; i++) g_bt[b * TT + tid + i * 256] = e[i] * inv;
}
__global__ __launch_bounds__(256) void k_hpart(const float* __restrict__ C) {
    __shared__ float bts[TT / NCHUNK];
    int b = blockIdx.y, chunk = blockIdx.x;
    int tid = threadIdx.x;
    if (tid < TT / NCHUNK) bts[tid] = g_bt[b * TT + chunk * (TT / NCHUNK) + tid];
    __syncthreads();
    float a0 = 0.f, a1 = 0.f;
    for (int tt = 0; tt < TT / NCHUNK; tt++) {
        int t = chunk * (TT / NCHUNK) + tt;
        const float* cr = C + ((size_t)(b * TT + t)) * DD;
        a0 = fmaf(bts[tt], cr[tid], a0);
        a1 = fmaf(bts[tt], cr[tid + 256], a1);
    }
    g_hp[(b * NCHUNK + chunk) * DD + tid] = a0;
    g_hp[(b * NCHUNK + chunk) * DD + tid + 256] = a1;
}
__global__ __launch_bounds__(512) void k_hcombine() {
    int b = blockIdx.x, d = threadIdx.x;
    float s = 0.f;
#pragma unroll
    for (int c = 0; c < NCHUNK; c++) s += g_hp[(b * NCHUNK + c) * DD + d];
    g_h[b * DD + d] = s;
}

// ---------------- P split: P = exp(S - M)*invZ -> fp16 g_Ph ------------------
__global__ __launch_bounds__(256) void k_psplit() {
    size_t base = ((size_t)blockIdx.x * 256 + threadIdx.x) * 8;
    int j = (int)(base & (JJ - 1));
    int row = (int)(base >> 8);
    int b = row >> 10;
    float4 v0 = *(const float4*)(g_S + base);
    float4 v1 = *(const float4*)(g_S + base + 4);
    float4 M0 = *(const float4*)(g_M + b * JJ + j);
    float4 M1 = *(const float4*)(g_M + b * JJ + j + 4);
    float4 z0 = *(const float4*)(g_invZ + b * JJ + j);
    float4 z1 = *(const float4*)(g_invZ + b * JJ + j + 4);
    float v[8];
    v[0] = __expf(v0.x - M0.x) * z0.x;
    v[1] = __expf(v0.y - M0.y) * z0.y;
    v[2] = __expf(v0.z - M0.z) * z0.z;
    v[3] = __expf(v0.w - M0.w) * z0.w;
    v[4] = __expf(v1.x - M1.x) * z1.x;
    v[5] = __expf(v1.y - M1.y) * z1.y;
    v[6] = __expf(v1.z - M1.z) * z1.z;
    v[7] = __expf(v1.w - M1.w) * z1.w;
    uint4 hi;
    cvtf16_8(v, &hi);
    *(uint4*)(g_Ph + base) = hi;
}

// ---------------- U-GEMM: U[128t x 128d] = P @ Q, full G epilogue ------------
// Pipeline uses first 32KB (2 x 16KB stages); epilogue staging reuses full 64KB.
#define UG_STAGE 16384
#define UG_BH 8192
#define UG_DSMEM 65536
__global__ __launch_bounds__(256, 2) void k_u_mma(const float* __restrict__ C,
                                                  float* __restrict__ G) {
    extern __shared__ __align__(16) char dsm[];
    __shared__ float hs[128];

    const int tid = threadIdx.x, lane = tid & 31, wid = tid >> 5;
    const int b = blockIdx.z, t0 = blockIdx.y * 128, d0 = blockIdx.x * 128;

    if (tid < 128) hs[tid] = g_h[b * DD + d0 + tid];
    __syncthreads();

    const uint32_t smb = smem_u32(dsm);
    const int sr = tid >> 2, sc = tid & 3;
    const int ssw = (sr >> 1) & 3;
    const int rB = tid >> 4, cB = tid & 15;
    const int bsw = rB & 7;
    const __half* Pb = g_Ph + ((size_t)(b * TT + t0 + sr)) * JJ + sc * 8;
    const __half* Qb = g_Qh + ((size_t)(b * JJ + rB)) * DD + d0 + cB * 8;
    const uint32_t stsA = sr * 64 + ((sc ^ ssw) << 4);
    const uint32_t stsB = (((cB ^ bsw) & 7) | (cB & 8)) << 4;

    uint4 ra0, ra1, rb0, rb1;
    {
        ra0 = *(const uint4*)(Pb);
        ra1 = *(const uint4*)(Pb + (size_t)64 * JJ);
        rb0 = *(const uint4*)(Qb);
        rb1 = *(const uint4*)(Qb + (size_t)16 * DD);
    }
    {
        *(uint4*)(dsm + stsA) = ra0;
        *(uint4*)(dsm + stsA + 64 * 64) = ra1;
        *(uint4*)(dsm + UG_BH + rB * 256 + stsB) = rb0;
        *(uint4*)(dsm + UG_BH + (rB + 16) * 256 + stsB) = rb1;
    }
    {
        ra0 = *(const uint4*)(Pb + 32);
        ra1 = *(const uint4*)(Pb + 32 + (size_t)64 * JJ);
        rb0 = *(const uint4*)(Qb + (size_t)32 * DD);
        rb1 = *(const uint4*)(Qb + (size_t)48 * DD);
    }
    __syncthreads();

    const int wm = wid >> 2, wn = wid & 3;
    float acc[4][4][4];
#pragma unroll
    for (int i = 0; i < 4; i++)
#pragma unroll
        for (int j = 0; j < 4; j++)
#pragma unroll
            for (int e = 0; e < 4; e++) acc[i][j][e] = 0.f;

    const int lsw = lane & 7;
    const int arow = wm * 64 + (lane & 7) + ((lane >> 3) & 1) * 8;
    const int aswz = (arow >> 1) & 3;
    const int ack = lane >> 4;
    const int bkrow = (lane & 7) + ((lane >> 3) & 1) * 8;
    const int bcn = wn * 4 + (lane >> 4);

#pragma unroll 1
    for (int kc = 0; kc < 8; kc++) {
        if (kc < 7) {
            char* st = dsm + ((kc + 1) & 1) * UG_STAGE;
            *(uint4*)(st + stsA) = ra0;
            *(uint4*)(st + stsA + 64 * 64) = ra1;
            *(uint4*)(st + UG_BH + rB * 256 + stsB) = rb0;
            *(uint4*)(st + UG_BH + (rB + 16) * 256 + stsB) = rb1;
        }
        if (kc < 6) {
            ra0 = *(const uint4*)(Pb + (kc + 2) * 32);
            ra1 = *(const uint4*)(Pb + (kc + 2) * 32 + (size_t)64 * JJ);
            rb0 = *(const uint4*)(Qb + (size_t)(kc + 2) * 32 * DD);
            rb1 = *(const uint4*)(Qb + (size_t)((kc + 2) * 32 + 16) * DD);
        }
        const uint32_t sb = smb + (kc & 1) * UG_STAGE;
#pragma unroll
        for (int ks = 0; ks < 2; ks++) {
            uint32_t Af[4][4], Bf[2][4];
            const int ca = ks * 2 + ack;
            const int krow = ks * 16 + bkrow;
#pragma unroll
            for (int mi = 0; mi < 4; mi++)
                ldmx4(Af[mi], sb + (uint32_t)(arow + mi * 16) * 64 + ((ca ^ aswz) << 4));
#pragma unroll
            for (int n2 = 0; n2 < 2; n2++) {
                const int cn = bcn + n2 * 2;
                const uint32_t co = ((((cn ^ lsw) & 7) | (cn & 8)) << 4);
                ldmx4t(Bf[n2], sb + UG_BH + krow * 256 + co);
            }
#pragma unroll
            for (int mi = 0; mi < 4; mi++)
#pragma unroll
                for (int ni = 0; ni < 4; ni++) {
                    const uint32_t* bp = &Bf[ni >> 1][(ni & 1) * 2];
                    mma_f16(acc[mi][ni], Af[mi], bp[0], bp[1]);
                }
        }
        __syncthreads();
    }

    // stage U in smem (full 64KB region), then coalesced G epilogue
    float* st = (float*)dsm;
    const int g = lane >> 2, tc = (lane & 3) * 2;
#pragma unroll
    for (int mi = 0; mi < 4; mi++) {
        const int r0 = wm * 64 + mi * 16 + g;
#pragma unroll
        for (int ni = 0; ni < 4; ni++) {
            const int cl = wn * 32 + ni * 8 + tc;
            st[r0 * 128 + cl] = acc[mi][ni][0];
            st[r0 * 128 + cl + 1] = acc[mi][ni][1];
            st[(r0 + 8) * 128 + cl] = acc[mi][ni][2];
            st[(r0 + 8) * 128 + cl + 1] = acc[mi][ni][3];
        }
    }
    __syncthreads();
#pragma unroll
    for (int it = 0; it < 16; it++) {
        const int idx = it * 256 + tid;
        const int r = idx >> 5, c4 = (idx & 31) * 4;
        float4 u4 = *(float4*)&st[r * 128 + c4];
        float4 cv = *(const float4*)(C + ((size_t)(b * TT + t0 + r)) * DD + d0 + c4);
        float4 h4 = *(const float4*)&hs[c4];
        float* grow = G + ((size_t)(b * TT + t0 + r)) * (4 * DD);
        *(float4*)(grow + d0 + c4) = cv;
        *(float4*)(grow + DD + d0 + c4) = u4;
        *(float4*)(grow + 2 * DD + d0 + c4) =
            make_float4(cv.x * u4.x, cv.y * u4.y, cv.z * u4.z, cv.w * u4.w);
        *(float4*)(grow + 3 * DD + d0 + c4) =
            make_float4(cv.x * h4.x, cv.y * h4.y, cv.z * h4.z, cv.w * h4.w);
    }
}

// ---------------- launch ----------------------------------------------------
extern "C" void kernel_launch(void* const* d_in, const int* in_sizes, int n_in,
                              void* d_out, int out_size) {
    const float* C  = (const float*)d_in[0];
    const float* Q  = (const float*)d_in[1];
    const float* wa = (const float*)d_in[2];
    float* G = (float*)d_out;

    cudaFuncSetAttribute(k_s_mma, cudaFuncAttributeMaxDynamicSharedMemorySize, 2 * SG_STAGE);
    cudaFuncSetAttribute(k_u_mma, cudaFuncAttributeMaxDynamicSharedMemorySize, UG_DSMEM);

    float* d_q2; cudaGetSymbolAddress((void**)&d_q2, g_q2);

    k_prepQ<<<(BB * JJ) / 8, 256>>>(Q, wa + DD, d_q2);

    dim3 gs(JJ / 128, TT / 128, BB);
    k_s_mma<<<gs, 256, 2 * SG_STAGE>>>(C, wa);

    k_stats<<<BB, 256>>>();
    dim3 g2(NCHUNK, BB);
    k_hpart<<<g2, 256>>>(C);
    k_hcombine<<<BB, 512>>>();
    k_psplit<<<(BB * TT * JJ) / 8 / 256, 256>>>();

    dim3 gu(DD / 128, TT / 128, BB);
    k_u_mma<<<gu, 256, UG_DSMEM>>>(C, G);
}

// round 16
// speedup vs baseline: 1.0335x; 1.0335x over previous
#include <cuda_runtime.h>
#include <cuda_bf16.h>
#include <cuda_fp16.h>
#include <math.h>
#include <stdint.h>

#define BB 32
#define TT 1024
#define JJ 256
#define DD 512
#define NCHUNK 8
#define NHCH 32

// ---------------- scratch (device globals) ----------------------------------
__device__ float g_S[BB * TT * JJ];      // raw S (32 MB)
__device__ __half g_Qh[BB * JJ * DD];    // Q pre-converted to fp16 (8 MB)
__device__ __half g_Ph[BB * TT * JJ];    // P = softmax(S) fp16 (16 MB)
__device__ float g_q2[BB * JJ];
__device__ float g_mp[BB * 2 * TT];      // row-max partials (per j-tile)
__device__ float g_pM[BB * NCHUNK * JJ];
__device__ float g_pZ[BB * NCHUNK * JJ];
__device__ float g_M[BB * JJ];
__device__ float g_invZ[BB * JJ];
__device__ float g_bt[BB * TT];
__device__ float g_hp2[BB * NHCH * DD];  // h partials (32 chunks)
__device__ float g_h[BB * DD];

// ---------------- helpers ----------------------------------------------------
__device__ __forceinline__ uint32_t smem_u32(const void* p) {
    uint32_t a;
    asm("{ .reg .u64 t; cvta.to.shared.u64 t, %1; cvt.u32.u64 %0, t; }" : "=r"(a) : "l"(p));
    return a;
}
__device__ __forceinline__ void ldmx4(uint32_t* r, uint32_t a) {
    asm volatile("ldmatrix.sync.aligned.m8n8.x4.shared.b16 {%0,%1,%2,%3}, [%4];"
                 : "=r"(r[0]), "=r"(r[1]), "=r"(r[2]), "=r"(r[3]) : "r"(a));
}
__device__ __forceinline__ void ldmx4t(uint32_t* r, uint32_t a) {
    asm volatile("ldmatrix.sync.aligned.m8n8.x4.trans.shared.b16 {%0,%1,%2,%3}, [%4];"
                 : "=r"(r[0]), "=r"(r[1]), "=r"(r[2]), "=r"(r[3]) : "r"(a));
}
__device__ __forceinline__ void mma_f16(float* c, const uint32_t* a, uint32_t b0, uint32_t b1) {
    asm volatile(
        "mma.sync.aligned.m16n8k16.row.col.f32.f16.f16.f32 "
        "{%0,%1,%2,%3}, {%4,%5,%6,%7}, {%8,%9}, {%0,%1,%2,%3};"
        : "+f"(c[0]), "+f"(c[1]), "+f"(c[2]), "+f"(c[3])
        : "r"(a[0]), "r"(a[1]), "r"(a[2]), "r"(a[3]), "r"(b0), "r"(b1));
}
// fp16 convert 8 floats -> 16B
__device__ __forceinline__ void cvtf16_8(const float* v, uint4* hi) {
    uint32_t h[4];
#pragma unroll
    for (int p = 0; p < 4; p++)
        asm("cvt.rn.f16x2.f32 %0, %1, %2;" : "=r"(h[p]) : "f"(v[2 * p + 1]), "f"(v[2 * p]));
    *hi = make_uint4(h[0], h[1], h[2], h[3]);
}

// ---------------- prepQ: Qh = fp16(Q), q2 = Q @ w2 (one pass) ----------------
__global__ __launch_bounds__(256) void k_prepQ(const float* __restrict__ Q,
                                               const float* __restrict__ w2,
                                               float* __restrict__ q2out) {
    const int wid = threadIdx.x >> 5, lane = threadIdx.x & 31;
    const int row = blockIdx.x * 8 + wid;
    const float* src = Q + (size_t)row * DD;
    __half* dst = g_Qh + (size_t)row * DD;
    float s = 0.f;
#pragma unroll
    for (int h = 0; h < 2; h++) {
        const int c = h * 256 + lane * 8;
        float4 v0 = *(const float4*)(src + c);
        float4 v1 = *(const float4*)(src + c + 4);
        float v[8] = {v0.x, v0.y, v0.z, v0.w, v1.x, v1.y, v1.z, v1.w};
#pragma unroll
        for (int e = 0; e < 8; e++) s = fmaf(v[e], __ldg(&w2[c + e]), s);
        uint4 hi;
        cvtf16_8(v, &hi);
        *(uint4*)(dst + c) = hi;
    }
#pragma unroll
    for (int o = 16; o > 0; o >>= 1) s += __shfl_down_sync(0xffffffffu, s, o);
    if (lane == 0) q2out[row] = s;
}

// ---------------- S-GEMM: S = (C.*w3)@Q^T + c1 + q2, fused c1 + stats --------
#define SG_STAGE 16384
#define SG_B_OFF 8192
__global__ __launch_bounds__(256, 2) void k_s_mma(const float* __restrict__ C,
                                                  const float* __restrict__ wa) {
    extern __shared__ __align__(16) char dsm[];
    __shared__ float w1s[512];
    __shared__ float w3s[512];
    __shared__ float c1s[128], q2s[128];
    __shared__ float sRM[4][128];
    __shared__ float sCM[2][128], sCZ[2][128];

    const int tid = threadIdx.x, lane = tid & 31, wid = tid >> 5;
    const int b = blockIdx.z, tb = blockIdx.y, jt = blockIdx.x;
    const int t0 = tb * 128, j0 = jt * 128;

    w1s[tid] = wa[tid];
    w1s[tid + 256] = wa[tid + 256];
    w3s[tid] = wa[1024 + tid];
    w3s[tid + 256] = wa[1024 + tid + 256];
    if (tid < 128) q2s[tid] = g_q2[b * JJ + j0 + tid];
    __syncthreads();

    const uint32_t smb = smem_u32(dsm);
    const int sr = tid >> 2, sc = tid & 3;
    const int ssw = (sr >> 1) & 3;
    const float* Ab = C + ((size_t)(b * TT + t0 + sr)) * DD + sc * 8;
    const __half* Bb = g_Qh + ((size_t)(b * JJ + j0 + sr)) * DD + sc * 8;
    const uint32_t stsA = sr * 64 + ((sc ^ ssw) << 4);
    const uint32_t stsB = SG_B_OFF + sr * 64 + ((sc ^ ssw) << 4);

    float cd0 = 0.f, cd1 = 0.f;   // c1 partial dots for rows sr, sr+64

    float ra[16];
    uint4 rb0, rb1;
    // load chunk 0
    {
        *(float4*)(ra) = *(const float4*)(Ab);
        *(float4*)(ra + 4) = *(const float4*)(Ab + 4);
        *(float4*)(ra + 8) = *(const float4*)(Ab + (size_t)64 * DD);
        *(float4*)(ra + 12) = *(const float4*)(Ab + (size_t)64 * DD + 4);
        rb0 = *(const uint4*)(Bb);
        rb1 = *(const uint4*)(Bb + (size_t)64 * DD);
    }
    // convert/stage chunk 0 -> stage 0 (+ c1 accumulation)
    {
        const float* w = &w3s[sc * 8];
        const float* w1 = &w1s[sc * 8];
        float va[8];
        uint4 hi;
#pragma unroll
        for (int e = 0; e < 8; e++) { cd0 = fmaf(ra[e], w1[e], cd0); va[e] = ra[e] * w[e]; }
        cvtf16_8(va, &hi);
        *(uint4*)(dsm + stsA) = hi;
#pragma unroll
        for (int e = 0; e < 8; e++) { cd1 = fmaf(ra[8 + e], w1[e], cd1); va[e] = ra[8 + e] * w[e]; }
        cvtf16_8(va, &hi);
        *(uint4*)(dsm + stsA + 64 * 64) = hi;
        *(uint4*)(dsm + stsB) = rb0;
        *(uint4*)(dsm + stsB + 64 * 64) = rb1;
    }
    // load chunk 1
    {
        const float* pa = Ab + 32;
        *(float4*)(ra) = *(const float4*)(pa);
        *(float4*)(ra + 4) = *(const float4*)(pa + 4);
        *(float4*)(ra + 8) = *(const float4*)(pa + (size_t)64 * DD);
        *(float4*)(ra + 12) = *(const float4*)(pa + (size_t)64 * DD + 4);
        rb0 = *(const uint4*)(Bb + 32);
        rb1 = *(const uint4*)(Bb + 32 + (size_t)64 * DD);
    }
    __syncthreads();

    const int wm = wid >> 2, wn = wid & 3;
    float acc[4][4][4];
#pragma unroll
    for (int i = 0; i < 4; i++)
#pragma unroll
        for (int j = 0; j < 4; j++)
#pragma unroll
            for (int e = 0; e < 4; e++) acc[i][j][e] = 0.f;

    const int arow = wm * 64 + (lane & 7) + ((lane >> 3) & 1) * 8;
    const int aswz = (arow >> 1) & 3;
    const int ack = lane >> 4;
    const int bj = wn * 32 + (lane & 7) + ((lane >> 4) & 1) * 8;
    const int bsw3 = (bj >> 1) & 3;
    const int bck = (lane >> 3) & 1;

#pragma unroll 1
    for (int kc = 0; kc < 16; kc++) {
        if (kc < 15) {
            char* st = dsm + ((kc + 1) & 1) * SG_STAGE;
            const float* w = &w3s[(kc + 1) * 32 + sc * 8];
            const float* w1 = &w1s[(kc + 1) * 32 + sc * 8];
            float va[8];
            uint4 hi;
#pragma unroll
            for (int e = 0; e < 8; e++) { cd0 = fmaf(ra[e], w1[e], cd0); va[e] = ra[e] * w[e]; }
            cvtf16_8(va, &hi);
            *(uint4*)(st + stsA) = hi;
#pragma unroll
            for (int e = 0; e < 8; e++) { cd1 = fmaf(ra[8 + e], w1[e], cd1); va[e] = ra[8 + e] * w[e]; }
            cvtf16_8(va, &hi);
            *(uint4*)(st + stsA + 64 * 64) = hi;
            *(uint4*)(st + stsB) = rb0;
            *(uint4*)(st + stsB + 64 * 64) = rb1;
        }
        if (kc < 14) {
            const float* pa = Ab + (kc + 2) * 32;
            *(float4*)(ra) = *(const float4*)(pa);
            *(float4*)(ra + 4) = *(const float4*)(pa + 4);
            *(float4*)(ra + 8) = *(const float4*)(pa + (size_t)64 * DD);
            *(float4*)(ra + 12) = *(const float4*)(pa + (size_t)64 * DD + 4);
            rb0 = *(const uint4*)(Bb + (kc + 2) * 32);
            rb1 = *(const uint4*)(Bb + (kc + 2) * 32 + (size_t)64 * DD);
        }
        const uint32_t sb = smb + (kc & 1) * SG_STAGE;
#pragma unroll
        for (int ks = 0; ks < 2; ks++) {
            uint32_t Af[4][4], Bf[2][4];
            const int ca = ks * 2 + ack;
            const int cb = ks * 2 + bck;
#pragma unroll
            for (int mi = 0; mi < 4; mi++)
                ldmx4(Af[mi], sb + (uint32_t)(arow + mi * 16) * 64 + ((ca ^ aswz) << 4));
#pragma unroll
            for (int n2 = 0; n2 < 2; n2++)
                ldmx4(Bf[n2], sb + SG_B_OFF + (uint32_t)(bj + n2 * 16) * 64 + ((cb ^ bsw3) << 4));
#pragma unroll
            for (int mi = 0; mi < 4; mi++)
#pragma unroll
                for (int ni = 0; ni < 4; ni++) {
                    const uint32_t* bp = &Bf[ni >> 1][(ni & 1) * 2];
                    mma_f16(acc[mi][ni], Af[mi], bp[0], bp[1]);
                }
        }
        __syncthreads();
    }

    // reduce c1 partials across the 4 sc-threads of each row
    cd0 += __shfl_xor_sync(0xffffffffu, cd0, 1);
    cd0 += __shfl_xor_sync(0xffffffffu, cd0, 2);
    cd1 += __shfl_xor_sync(0xffffffffu, cd1, 1);
    cd1 += __shfl_xor_sync(0xffffffffu, cd1, 2);
    if ((tid & 3) == 0) {
        c1s[sr] = cd0;
        c1s[sr + 64] = cd1;
    }
    __syncthreads();

    // ---- epilogue: biases, store S, fused row-max + column partial stats ----
    const int g = lane >> 2, tc = (lane & 3) * 2;
#pragma unroll
    for (int mi = 0; mi < 4; mi++) {
        const int tl = wm * 64 + mi * 16 + g;
        const float c1a = c1s[tl], c1b = c1s[tl + 8];
        float* row0 = &g_S[((size_t)(b * TT + t0 + tl)) * JJ + j0];
        float* row1 = row0 + (size_t)8 * JJ;
#pragma unroll
        for (int ni = 0; ni < 4; ni++) {
            const int jl = wn * 32 + ni * 8 + tc;
            const float q2a = q2s[jl], q2b = q2s[jl + 1];
            acc[mi][ni][0] += c1a + q2a;
            acc[mi][ni][1] += c1a + q2b;
            acc[mi][ni][2] += c1b + q2a;
            acc[mi][ni][3] += c1b + q2b;
            *(float2*)(row0 + jl) = make_float2(acc[mi][ni][0], acc[mi][ni][1]);
            *(float2*)(row1 + jl) = make_float2(acc[mi][ni][2], acc[mi][ni][3]);
        }
    }
#pragma unroll
    for (int mi = 0; mi < 4; mi++) {
#pragma unroll
        for (int rr = 0; rr < 2; rr++) {
            float m = -1e30f;
#pragma unroll
            for (int ni = 0; ni < 4; ni++)
                m = fmaxf(m, fmaxf(acc[mi][ni][rr * 2], acc[mi][ni][rr * 2 + 1]));
            m = fmaxf(m, __shfl_xor_sync(0xffffffffu, m, 1));
            m = fmaxf(m, __shfl_xor_sync(0xffffffffu, m, 2));
            if ((lane & 3) == 0) sRM[wn][wm * 64 + mi * 16 + g + rr * 8] = m;
        }
    }
#pragma unroll
    for (int ni = 0; ni < 4; ni++) {
#pragma unroll
        for (int cc = 0; cc < 2; cc++) {
            float m = -1e30f;
#pragma unroll
            for (int mi = 0; mi < 4; mi++)
                m = fmaxf(m, fmaxf(acc[mi][ni][cc], acc[mi][ni][2 + cc]));
            float z = 0.f;
#pragma unroll
            for (int mi = 0; mi < 4; mi++)
                z += __expf(acc[mi][ni][cc] - m) + __expf(acc[mi][ni][2 + cc] - m);
#pragma unroll
            for (int o = 4; o < 32; o <<= 1) {
                float Mo = __shfl_xor_sync(0xffffffffu, m, o);
                float Zo = __shfl_xor_sync(0xffffffffu, z, o);
                float nm = fmaxf(m, Mo);
                z = z * __expf(m - nm) + Zo * __expf(Mo - nm);
                m = nm;
            }
            if (g == 0) {
                sCM[wm][wn * 32 + ni * 8 + tc + cc] = m;
                sCZ[wm][wn * 32 + ni * 8 + tc + cc] = z;
            }
        }
    }
    __syncthreads();
    if (tid < 128) {
        float m = fmaxf(fmaxf(sRM[0][tid], sRM[1][tid]), fmaxf(sRM[2][tid], sRM[3][tid]));
        g_mp[((size_t)(b * 2 + jt)) * TT + t0 + tid] = m;
        float M0 = sCM[0][tid], M1 = sCM[1][tid];
        float nm = fmaxf(M0, M1);
        float Z = sCZ[0][tid] * __expf(M0 - nm) + sCZ[1][tid] * __expf(M1 - nm);
        g_pM[(b * NCHUNK + tb) * JJ + j0 + tid] = nm;
        g_pZ[(b * NCHUNK + tb) * JJ + j0 + tid] = Z;
    }
}

// ---------------- merged stats: colcombine + bt -------------------------------
__global__ __launch_bounds__(256) void k_stats() {
    __shared__ float red[256];
    int b = blockIdx.x, tid = threadIdx.x;
    {
        int j = tid;
        float M = -1e30f;
#pragma unroll
        for (int c = 0; c < NCHUNK; c++) M = fmaxf(M, g_pM[(b * NCHUNK + c) * JJ + j]);
        float Z = 0.f;
#pragma unroll
        for (int c = 0; c < NCHUNK; c++)
            Z += g_pZ[(b * NCHUNK + c) * JJ + j] * __expf(g_pM[(b * NCHUNK + c) * JJ + j] - M);
        g_M[b * JJ + j] = M;
        g_invZ[b * JJ + j] = 1.0f / Z;
    }
    float mv[4];
#pragma unroll
    for (int i = 0; i < 4; i++) {
        int t = tid + i * 256;
        mv[i] = fmaxf(g_mp[((size_t)(b * 2)) * TT + t], g_mp[((size_t)(b * 2 + 1)) * TT + t]);
    }
    float mx = fmaxf(fmaxf(mv[0], mv[1]), fmaxf(mv[2], mv[3]));
    red[tid] = mx;
    __syncthreads();
    for (int s = 128; s > 0; s >>= 1) {
        if (tid < s) red[tid] = fmaxf(red[tid], red[tid + s]);
        __syncthreads();
    }
    float bmax = red[0];
    __syncthreads();
    float e[4], ssum = 0.f;
#pragma unroll
    for (int i = 0; i < 4; i++) { e[i] = __expf(mv[i] - bmax); ssum += e[i]; }
    red[tid] = ssum;
    __syncthreads();
    for (int s = 128; s > 0; s >>= 1) {
        if (tid < s) red[tid] += red[tid + s];
        __syncthreads();
    }
    float inv = 1.0f / red[0];
#pragma unroll
    for (int i = 0; i < 4; i++) g_bt[b * TT + tid + i * 256] = e[i] * inv;
}

// ---------------- h partials: 32 chunks for full-chip occupancy ---------------
__global__ __launch_bounds__(256) void k_hpart(const float* __restrict__ C) {
    __shared__ float bts[TT / NHCH];
    int b = blockIdx.y, chunk = blockIdx.x;
    int tid = threadIdx.x;
    if (tid < TT / NHCH) bts[tid] = g_bt[b * TT + chunk * (TT / NHCH) + tid];
    __syncthreads();
    float a0 = 0.f, a1 = 0.f;
    for (int tt = 0; tt < TT / NHCH; tt++) {
        int t = chunk * (TT / NHCH) + tt;
        const float* cr = C + ((size_t)(b * TT + t)) * DD;
        a0 = fmaf(bts[tt], cr[tid], a0);
        a1 = fmaf(bts[tt], cr[tid + 256], a1);
    }
    g_hp2[(b * NHCH + chunk) * DD + tid] = a0;
    g_hp2[(b * NHCH + chunk) * DD + tid + 256] = a1;
}
__global__ __launch_bounds__(512) void k_hcombine() {
    int b = blockIdx.x, d = threadIdx.x;
    float s = 0.f;
#pragma unroll
    for (int c = 0; c < NHCH; c++) s += g_hp2[(b * NHCH + c) * DD + d];
    g_h[b * DD + d] = s;
}

// ---------------- P split: P = exp(S - M)*invZ -> fp16 g_Ph ------------------
__global__ __launch_bounds__(256) void k_psplit() {
    size_t base = ((size_t)blockIdx.x * 256 + threadIdx.x) * 8;
    int j = (int)(base & (JJ - 1));
    int row = (int)(base >> 8);
    int b = row >> 10;
    float4 v0 = *(const float4*)(g_S + base);
    float4 v1 = *(const float4*)(g_S + base + 4);
    float4 M0 = *(const float4*)(g_M + b * JJ + j);
    float4 M1 = *(const float4*)(g_M + b * JJ + j + 4);
    float4 z0 = *(const float4*)(g_invZ + b * JJ + j);
    float4 z1 = *(const float4*)(g_invZ + b * JJ + j + 4);
    float v[8];
    v[0] = __expf(v0.x - M0.x) * z0.x;
    v[1] = __expf(v0.y - M0.y) * z0.y;
    v[2] = __expf(v0.z - M0.z) * z0.z;
    v[3] = __expf(v0.w - M0.w) * z0.w;
    v[4] = __expf(v1.x - M1.x) * z1.x;
    v[5] = __expf(v1.y - M1.y) * z1.y;
    v[6] = __expf(v1.z - M1.z) * z1.z;
    v[7] = __expf(v1.w - M1.w) * z1.w;
    uint4 hi;
    cvtf16_8(v, &hi);
    *(uint4*)(g_Ph + base) = hi;
}

// ---------------- U-GEMM: U[128t x 128d] = P @ Q, full G epilogue ------------
// Pipeline uses first 32KB (2 x 16KB stages); epilogue staging reuses full 64KB.
#define UG_STAGE 16384
#define UG_BH 8192
#define UG_DSMEM 65536
__global__ __launch_bounds__(256, 2) void k_u_mma(const float* __restrict__ C,
                                                  float* __restrict__ G) {
    extern __shared__ __align__(16) char dsm[];
    __shared__ float hs[128];

    const int tid = threadIdx.x, lane = tid & 31, wid = tid >> 5;
    const int b = blockIdx.z, t0 = blockIdx.y * 128, d0 = blockIdx.x * 128;

    if (tid < 128) hs[tid] = g_h[b * DD + d0 + tid];
    __syncthreads();

    const uint32_t smb = smem_u32(dsm);
    const int sr = tid >> 2, sc = tid & 3;
    const int ssw = (sr >> 1) & 3;
    const int rB = tid >> 4, cB = tid & 15;
    const int bsw = rB & 7;
    const __half* Pb = g_Ph + ((size_t)(b * TT + t0 + sr)) * JJ + sc * 8;
    const __half* Qb = g_Qh + ((size_t)(b * JJ + rB)) * DD + d0 + cB * 8;
    const uint32_t stsA = sr * 64 + ((sc ^ ssw) << 4);
    const uint32_t stsB = (((cB ^ bsw) & 7) | (cB & 8)) << 4;

    uint4 ra0, ra1, rb0, rb1;
    {
        ra0 = *(const uint4*)(Pb);
        ra1 = *(const uint4*)(Pb + (size_t)64 * JJ);
        rb0 = *(const uint4*)(Qb);
        rb1 = *(const uint4*)(Qb + (size_t)16 * DD);
    }
    {
        *(uint4*)(dsm + stsA) = ra0;
        *(uint4*)(dsm + stsA + 64 * 64) = ra1;
        *(uint4*)(dsm + UG_BH + rB * 256 + stsB) = rb0;
        *(uint4*)(dsm + UG_BH + (rB + 16) * 256 + stsB) = rb1;
    }
    {
        ra0 = *(const uint4*)(Pb + 32);
        ra1 = *(const uint4*)(Pb + 32 + (size_t)64 * JJ);
        rb0 = *(const uint4*)(Qb + (size_t)32 * DD);
        rb1 = *(const uint4*)(Qb + (size_t)48 * DD);
    }
    __syncthreads();

    const int wm = wid >> 2, wn = wid & 3;
    float acc[4][4][4];
#pragma unroll
    for (int i = 0; i < 4; i++)
#pragma unroll
        for (int j = 0; j < 4; j++)
#pragma unroll
            for (int e = 0; e < 4; e++) acc[i][j][e] = 0.f;

    const int lsw = lane & 7;
    const int arow = wm * 64 + (lane & 7) + ((lane >> 3) & 1) * 8;
    const int aswz = (arow >> 1) & 3;
    const int ack = lane >> 4;
    const int bkrow = (lane & 7) + ((lane >> 3) & 1) * 8;
    const int bcn = wn * 4 + (lane >> 4);

#pragma unroll 1
    for (int kc = 0; kc < 8; kc++) {
        if (kc < 7) {
            char* st = dsm + ((kc + 1) & 1) * UG_STAGE;
            *(uint4*)(st + stsA) = ra0;
            *(uint4*)(st + stsA + 64 * 64) = ra1;
            *(uint4*)(st + UG_BH + rB * 256 + stsB) = rb0;
            *(uint4*)(st + UG_BH + (rB + 16) * 256 + stsB) = rb1;
        }
        if (kc < 6) {
            ra0 = *(const uint4*)(Pb + (kc + 2) * 32);
            ra1 = *(const uint4*)(Pb + (kc + 2) * 32 + (size_t)64 * JJ);
            rb0 = *(const uint4*)(Qb + (size_t)(kc + 2) * 32 * DD);
            rb1 = *(const uint4*)(Qb + (size_t)((kc + 2) * 32 + 16) * DD);
        }
        const uint32_t sb = smb + (kc & 1) * UG_STAGE;
#pragma unroll
        for (int ks = 0; ks < 2; ks++) {
            uint32_t Af[4][4], Bf[2][4];
            const int ca = ks * 2 + ack;
            const int krow = ks * 16 + bkrow;
#pragma unroll
            for (int mi = 0; mi < 4; mi++)
                ldmx4(Af[mi], sb + (uint32_t)(arow + mi * 16) * 64 + ((ca ^ aswz) << 4));
#pragma unroll
            for (int n2 = 0; n2 < 2; n2++) {
                const int cn = bcn + n2 * 2;
                const uint32_t co = ((((cn ^ lsw) & 7) | (cn & 8)) << 4);
                ldmx4t(Bf[n2], sb + UG_BH + krow * 256 + co);
            }
#pragma unroll
            for (int mi = 0; mi < 4; mi++)
#pragma unroll
                for (int ni = 0; ni < 4; ni++) {
                    const uint32_t* bp = &Bf[ni >> 1][(ni & 1) * 2];
                    mma_f16(acc[mi][ni], Af[mi], bp[0], bp[1]);
                }
        }
        __syncthreads();
    }

    // stage U in smem (full 64KB region), then coalesced G epilogue
    float* st = (float*)dsm;
    const int g = lane >> 2, tc = (lane & 3) * 2;
#pragma unroll
    for (int mi = 0; mi < 4; mi++) {
        const int r0 = wm * 64 + mi * 16 + g;
#pragma unroll
        for (int ni = 0; ni < 4; ni++) {
            const int cl = wn * 32 + ni * 8 + tc;
            st[r0 * 128 + cl] = acc[mi][ni][0];
            st[r0 * 128 + cl + 1] = acc[mi][ni][1];
            st[(r0 + 8) * 128 + cl] = acc[mi][ni][2];
            st[(r0 + 8) * 128 + cl + 1] = acc[mi][ni][3];
        }
    }
    __syncthreads();
#pragma unroll
    for (int it = 0; it < 16; it++) {
        const int idx = it * 256 + tid;
        const int r = idx >> 5, c4 = (idx & 31) * 4;
        float4 u4 = *(float4*)&st[r * 128 + c4];
        float4 cv = *(const float4*)(C + ((size_t)(b * TT + t0 + r)) * DD + d0 + c4);
        float4 h4 = *(const float4*)&hs[c4];
        float* grow = G + ((size_t)(b * TT + t0 + r)) * (4 * DD);
        *(float4*)(grow + d0 + c4) = cv;
        *(float4*)(grow + DD + d0 + c4) = u4;
        *(float4*)(grow + 2 * DD + d0 + c4) =
            make_float4(cv.x * u4.x, cv.y * u4.y, cv.z * u4.z, cv.w * u4.w);
        *(float4*)(grow + 3 * DD + d0 + c4) =
            make_float4(cv.x * h4.x, cv.y * h4.y, cv.z * h4.z, cv.w * h4.w);
    }
}

// ---------------- launch ----------------------------------------------------
extern "C" void kernel_launch(void* const* d_in, const int* in_sizes, int n_in,
                              void* d_out, int out_size) {
    const float* C  = (const float*)d_in[0];
    const float* Q  = (const float*)d_in[1];
    const float* wa = (const float*)d_in[2];
    float* G = (float*)d_out;

    cudaFuncSetAttribute(k_s_mma, cudaFuncAttributeMaxDynamicSharedMemorySize, 2 * SG_STAGE);
    cudaFuncSetAttribute(k_u_mma, cudaFuncAttributeMaxDynamicSharedMemorySize, UG_DSMEM);

    float* d_q2; cudaGetSymbolAddress((void**)&d_q2, g_q2);

    k_prepQ<<<(BB * JJ) / 8, 256>>>(Q, wa + DD, d_q2);

    dim3 gs(JJ / 128, TT / 128, BB);
    k_s_mma<<<gs, 256, 2 * SG_STAGE>>>(C, wa);

    k_stats<<<BB, 256>>>();
    dim3 g2(NHCH, BB);
    k_hpart<<<g2, 256>>>(C);
    k_hcombine<<<BB, 512>>>();
    k_psplit<<<(BB * TT * JJ) / 8 / 256, 256>>>();

    dim3 gu(DD / 128, TT / 128, BB);
    k_u_mma<<<gu, 256, UG_DSMEM>>>(C, G);
}